// round 1
// baseline (speedup 1.0000x reference)
#include <cuda_runtime.h>

typedef unsigned long long u64;

#define TPB   128
#define ELEMS 32
#define XSTR  785   // 784 + 1 pad: bank step 17 per element -> conflict-free strided LDS

// ---- packed fp32x2 helpers (sm_103a dual-fp32 path; 2x FFMA throughput) ----
__device__ __forceinline__ u64 pk(float lo, float hi) {
    u64 r; asm("mov.b64 %0, {%1, %2};" : "=l"(r) : "f"(lo), "f"(hi)); return r;
}
__device__ __forceinline__ void upk(float& lo, float& hi, u64 v) {
    asm("mov.b64 {%0, %1}, %2;" : "=f"(lo), "=f"(hi) : "l"(v));
}
__device__ __forceinline__ u64 fma2(u64 a, u64 b, u64 c) {
    u64 d; asm("fma.rn.f32x2 %0, %1, %2, %3;" : "=l"(d) : "l"(a), "l"(b), "l"(c)); return d;
}
__device__ __forceinline__ u64 add2(u64 a, u64 b) {
    u64 d; asm("add.rn.f32x2 %0, %1, %2;" : "=l"(d) : "l"(a), "l"(b)); return d;
}
__device__ __forceinline__ u64 shflx2(u64 v, int m) {
    float lo, hi; upk(lo, hi, v);
    lo = __shfl_xor_sync(0xffffffffu, lo, m);
    hi = __shfl_xor_sync(0xffffffffu, hi, m);
    return pk(lo, hi);
}

extern __shared__ __align__(16) float dynsmem[];

__global__ void __launch_bounds__(TPB) snn_kernel(
    const float* __restrict__ x,  const float* __restrict__ W1,
    const float* __restrict__ b1, const float* __restrict__ W2,
    const float* __restrict__ b2, float* __restrict__ out, int B)
{
    float* smx = dynsmem;                    // [ELEMS][XSTR]
    float* w1t = dynsmem + ELEMS * XSTR;     // [28][32]  (W1 transposed: [i][o])

    const int tid     = threadIdx.x;
    const int b_local = tid >> 2;            // 0..31 : element within block
    const int oq      = tid & 3;             // 0..3  : hidden-unit quarter
    const int obase   = oq << 3;             // first of 8 hidden units this thread owns
    const int b       = blockIdx.x * ELEMS + b_local;
    const int nElem   = min(ELEMS, B - blockIdx.x * ELEMS);

    // ---- stage W1 transposed into smem (coalesced read of W1[o][i]) ----
    for (int idx = tid; idx < 28 * 32; idx += TPB) {
        int o = idx / 28, i = idx % 28;
        w1t[i * 32 + o] = W1[idx];
    }
    // ---- stage 32 full images, perfectly coalesced (each byte read once) ----
    const float* gx = x + (size_t)blockIdx.x * ELEMS * 784;
    const int nload = nElem * 784;
    for (int idx = tid; idx < nload; idx += TPB) {
        smx[(idx / 784) * XSTR + (idx % 784)] = gx[idx];
    }

    // ---- per-thread register weights: layer 2 (W2[j][i] for i in [obase,obase+8)) ----
    u64 w2r[8][5], b2r[5], hb[4];
#pragma unroll
    for (int k = 0; k < 8; ++k) {
        int i = obase + k;
#pragma unroll
        for (int m = 0; m < 5; ++m)
            w2r[k][m] = pk(__ldg(&W2[(2 * m) * 32 + i]), __ldg(&W2[(2 * m + 1) * 32 + i]));
    }
#pragma unroll
    for (int m = 0; m < 5; ++m) b2r[m] = pk(__ldg(&b2[2 * m]), __ldg(&b2[2 * m + 1]));
#pragma unroll
    for (int m = 0; m < 4; ++m)
        hb[m] = pk(__ldg(&b1[obase + 2 * m]), __ldg(&b1[obase + 2 * m + 1]));

    __syncthreads();

    const float* xr  = smx + b_local * XSTR;
    const float* w1p = w1t + obase;

    u64 v1[4], v2[5], acc[5];
#pragma unroll
    for (int m = 0; m < 4; ++m) v1[m] = 0ull;        // 0.0f|0.0f
#pragma unroll
    for (int m = 0; m < 5; ++m) { v2[m] = 0ull; acc[m] = 0ull; }

#pragma unroll 1
    for (int t = 0; t < 28; ++t) {
        // ===== layer 1: h1[o] = b1[o] + sum_i x[b,i,t] * W1[o,i]  (8 o's, 4 f32x2) =====
        u64 h[4] = { hb[0], hb[1], hb[2], hb[3] };
#pragma unroll
        for (int i = 0; i < 28; ++i) {
            float xv = xr[i * 28 + t];               // broadcast LDS (conflict-free)
            u64 xd = pk(xv, xv);
            const ulonglong2* wp = reinterpret_cast<const ulonglong2*>(w1p + i * 32);
            ulonglong2 wa = wp[0];                   // weight pairs (o+0,o+1),(o+2,o+3)
            ulonglong2 wb = wp[1];                   // (o+4,o+5),(o+6,o+7)
            h[0] = fma2(xd, wa.x, h[0]);
            h[1] = fma2(xd, wa.y, h[1]);
            h[2] = fma2(xd, wb.x, h[2]);
            h[3] = fma2(xd, wb.y, h[3]);
        }

        // ===== IF neuron, layer 1 (v += h; spike = v>=1; hard reset) =====
        float s[8];
#pragma unroll
        for (int m = 0; m < 4; ++m) {
            v1[m] = add2(v1[m], h[m]);
            float vlo, vhi; upk(vlo, vhi, v1[m]);
            s[2 * m]     = (vlo >= 1.0f) ? 1.0f : 0.0f;
            s[2 * m + 1] = (vhi >= 1.0f) ? 1.0f : 0.0f;
            vlo = (vlo >= 1.0f) ? 0.0f : vlo;
            vhi = (vhi >= 1.0f) ? 0.0f : vhi;
            v1[m] = pk(vlo, vhi);
        }

        // ===== layer 2 partial: h2[j] += sum over this thread's 8 spikes =====
        u64 h2[5] = { 0ull, 0ull, 0ull, 0ull, 0ull };
#pragma unroll
        for (int k = 0; k < 8; ++k) {
            u64 sd = pk(s[k], s[k]);
#pragma unroll
            for (int m = 0; m < 5; ++m) h2[m] = fma2(sd, w2r[k][m], h2[m]);
        }

        // ===== quad butterfly reduce + bias + IF layer 2 + spike accumulation =====
#pragma unroll
        for (int m = 0; m < 5; ++m) {
            h2[m] = add2(h2[m], shflx2(h2[m], 1));
            h2[m] = add2(h2[m], shflx2(h2[m], 2));
            h2[m] = add2(h2[m], b2r[m]);
            v2[m] = add2(v2[m], h2[m]);
            float vlo, vhi; upk(vlo, vhi, v2[m]);
            float slo = (vlo >= 1.0f) ? 1.0f : 0.0f;
            float shi = (vhi >= 1.0f) ? 1.0f : 0.0f;
            vlo = (vlo >= 1.0f) ? 0.0f : vlo;
            vhi = (vhi >= 1.0f) ? 0.0f : vhi;
            v2[m] = pk(vlo, vhi);
            acc[m] = add2(acc[m], pk(slo, shi));
        }
    }

    // ===== write firing rates (mean over T=28) =====
    if (oq == 0 && b < B) {
        float2* op = reinterpret_cast<float2*>(out + (size_t)b * 10);
#pragma unroll
        for (int m = 0; m < 5; ++m) {
            float lo, hi; upk(lo, hi, acc[m]);
            op[m] = make_float2(lo * (1.0f / 28.0f), hi * (1.0f / 28.0f));
        }
    }
}

extern "C" void kernel_launch(void* const* d_in, const int* in_sizes, int n_in,
                              void* d_out, int out_size) {
    const float* x  = (const float*)d_in[0];
    const float* W1 = (const float*)d_in[1];
    const float* b1 = (const float*)d_in[2];
    const float* W2 = (const float*)d_in[3];
    const float* b2 = (const float*)d_in[4];
    float* out = (float*)d_out;

    int B = in_sizes[0] / 784;
    int smem = (ELEMS * XSTR + 28 * 32) * (int)sizeof(float);  // 104,064 B -> 2 blocks/SM

    cudaFuncSetAttribute(snn_kernel, cudaFuncAttributeMaxDynamicSharedMemorySize, smem);

    int grid = (B + ELEMS - 1) / ELEMS;
    snn_kernel<<<grid, TPB, smem>>>(x, W1, b1, W2, b2, out, B);
}

// round 2
// speedup vs baseline: 1.9513x; 1.9513x over previous
#include <cuda_runtime.h>

typedef unsigned long long u64;
typedef unsigned int u32;

#define TPB   128
#define EPB   8                   // elements per block (2 per warp)
#define TSTR  68                  // words per t-row (56 used + pad; keeps 16B align, odd/2 banks)
#define IMGW  (28 * TSTR)         // words per staged (dup'd, t-major) image = 1904
#define XWORDS (EPB * IMGW)       // 15232 words
#define NTAB  (8 * 16 * 10)       // nibble tables: [p][v][j]
#define SMEM_WORDS (XWORDS + NTAB + 16)   // +16 pad: inactive lanes (j up to 15) over-read safely

// ---- packed fp32x2 helpers ----
__device__ __forceinline__ u64 pk(float lo, float hi) {
    u64 r; asm("mov.b64 %0, {%1, %2};" : "=l"(r) : "f"(lo), "f"(hi)); return r;
}
__device__ __forceinline__ void upk(float& lo, float& hi, u64 v) {
    asm("mov.b64 {%0, %1}, %2;" : "=f"(lo), "=f"(hi) : "l"(v));
}
__device__ __forceinline__ u64 fma2(u64 a, u64 b, u64 c) {
    u64 d; asm("fma.rn.f32x2 %0, %1, %2, %3;" : "=l"(d) : "l"(a), "l"(b), "l"(c)); return d;
}
__device__ __forceinline__ u64 add2(u64 a, u64 b) {
    u64 d; asm("add.rn.f32x2 %0, %1, %2;" : "=l"(d) : "l"(a), "l"(b)); return d;
}

extern __shared__ __align__(16) u32 smem_raw[];

__global__ void __launch_bounds__(TPB, 3) snn_kernel(
    const float* __restrict__ x,  const float* __restrict__ W1,
    const float* __restrict__ b1, const float* __restrict__ W2,
    const float* __restrict__ b2, float* __restrict__ out, int B)
{
    float* smx = reinterpret_cast<float*>(smem_raw);   // dup'd t-major images
    float* tab = smx + XWORDS;                         // nibble LUT [p][v][j]

    const int tid  = threadIdx.x;
    const int lid  = tid & 31;
    const int wid  = tid >> 5;
    const int half = lid >> 4;        // 0 = elem A, 1 = elem B (within warp)
    const int u    = lid & 15;        // this lane owns hidden units u and u+16
    const int eLocal  = wid * 2 + half;
    const int eGlobal = blockIdx.x * EPB + eLocal;

    // ================= nibble LUT build (once per block, 5 KB) ==================
    // tab[(p*16+v)*10 + j] = sum_{b: bit b of v} W2[j][4p+b]  (ascending-k order)
    for (int idx = tid; idx < NTAB; idx += TPB) {
        int j = idx % 10;
        int v = (idx / 10) & 15;
        int p = idx / 160;
        float s = 0.0f;
#pragma unroll
        for (int b = 0; b < 4; ++b)
            if ((v >> b) & 1) s += W2[j * 32 + p * 4 + b];
        tab[idx] = s;
    }

    // ================= stage images: t-major, each x duplicated =================
    // task = (e, i): read x[e][i][0..27] (112B contiguous), write (x,x) pairs at
    // word (e*IMGW + t*TSTR + 2i). Fully-used 16B global loads, 8B smem stores.
    {
        const int base = blockIdx.x * EPB;
        for (int task = tid; task < EPB * 28; task += TPB) {
            int e = task / 28, i = task % 28;
            if (base + e < B) {
                const float4* src = reinterpret_cast<const float4*>(
                    x + (size_t)(base + e) * 784 + i * 28);
                float2* dst = reinterpret_cast<float2*>(smx + e * IMGW + 2 * i);
#pragma unroll
                for (int q = 0; q < 7; ++q) {
                    float4 v4 = src[q];
                    dst[(4 * q + 0) * (TSTR / 2)] = make_float2(v4.x, v4.x);
                    dst[(4 * q + 1) * (TSTR / 2)] = make_float2(v4.y, v4.y);
                    dst[(4 * q + 2) * (TSTR / 2)] = make_float2(v4.z, v4.z);
                    dst[(4 * q + 3) * (TSTR / 2)] = make_float2(v4.w, v4.w);
                }
            }
        }
    }

    // ================= per-lane register weights: W1 columns u, u+16 ============
    u64 w1pk[28];
    {
        const float4* p0 = reinterpret_cast<const float4*>(W1 + u * 28);
        const float4* p1 = reinterpret_cast<const float4*>(W1 + (u + 16) * 28);
#pragma unroll
        for (int q = 0; q < 7; ++q) {
            float4 a = __ldg(&p0[q]);
            float4 c = __ldg(&p1[q]);
            w1pk[4 * q + 0] = pk(a.x, c.x);
            w1pk[4 * q + 1] = pk(a.y, c.y);
            w1pk[4 * q + 2] = pk(a.z, c.z);
            w1pk[4 * q + 3] = pk(a.w, c.w);
        }
    }
    const u64 b1pk = pk(__ldg(&b1[u]), __ldg(&b1[u + 16]));
    const float b2j = (u < 10) ? __ldg(&b2[u]) : 0.0f;
    const float* tabj = tab + u;      // lanes u>=10 over-read into pad (harmless)

    __syncthreads();

    // ================= main recurrence ==========================================
    const float* xcol0 = smx + eLocal * IMGW;
    u64 v1 = 0ull;                    // packed membrane potentials (u, u+16)
    float v2 = 0.0f, acc = 0.0f;      // layer-2 state for output j=u (lanes 0..9)

#pragma unroll 1
    for (int t = 0; t < 28; ++t) {
        // ---- layer 1: h = b1 + sum_i x_i * w_i (sequential i: exact ref order) ----
        const ulonglong2* xc = reinterpret_cast<const ulonglong2*>(xcol0 + t * TSTR);
        u64 h = b1pk;
#pragma unroll
        for (int q = 0; q < 14; ++q) {
            ulonglong2 xp = xc[q];                 // ((x2q,x2q), (x2q+1,x2q+1))
            h = fma2(xp.x, w1pk[2 * q], h);
            h = fma2(xp.y, w1pk[2 * q + 1], h);
        }

        // ---- IF layer 1 + spike bitmask ----
        v1 = add2(v1, h);
        float vlo, vhi; upk(vlo, vhi, v1);
        bool slo = (vlo >= 1.0f), shi = (vhi >= 1.0f);
        u32 bL = __ballot_sync(0xffffffffu, slo);  // bit l = unit (l&15) of elem (l>>4)
        u32 bH = __ballot_sync(0xffffffffu, shi);  // bit l = unit (l&15)+16
        vlo = slo ? 0.0f : vlo;
        vhi = shi ? 0.0f : vhi;
        v1 = pk(vlo, vhi);
        u32 m = half ? ((bL >> 16) | (bH & 0xFFFF0000u))
                     : ((bL & 0xFFFFu) | (bH << 16));

        // ---- layer 2 via nibble LUT (lanes j<10 meaningful) ----
        float h2 = b2j;
#pragma unroll
        for (int p = 0; p < 8; ++p) {
            u32 n = (m >> (4 * p)) & 15u;
            h2 += tabj[(p * 16 + n) * 10];
        }

        // ---- IF layer 2 + rate accumulation ----
        v2 += h2;
        bool s2 = (v2 >= 1.0f);
        acc += s2 ? 1.0f : 0.0f;
        v2 = s2 ? 0.0f : v2;
    }

    if (u < 10 && eGlobal < B)
        out[eGlobal * 10 + u] = acc * (1.0f / 28.0f);
}

extern "C" void kernel_launch(void* const* d_in, const int* in_sizes, int n_in,
                              void* d_out, int out_size) {
    const float* x  = (const float*)d_in[0];
    const float* W1 = (const float*)d_in[1];
    const float* b1 = (const float*)d_in[2];
    const float* W2 = (const float*)d_in[3];
    const float* b2 = (const float*)d_in[4];
    float* out = (float*)d_out;

    int B = in_sizes[0] / 784;
    int smem = SMEM_WORDS * (int)sizeof(float);   // ~66.2 KB -> 3 blocks/SM

    cudaFuncSetAttribute(snn_kernel, cudaFuncAttributeMaxDynamicSharedMemorySize, smem);

    int grid = (B + EPB - 1) / EPB;
    snn_kernel<<<grid, TPB, smem>>>(x, W1, b1, W2, b2, out, B);
}

// round 3
// speedup vs baseline: 3.3119x; 1.6972x over previous
#include <cuda_runtime.h>

typedef unsigned long long u64;
typedef unsigned int u32;

#define TPB   128
#define EPW   4                    // elements per warp
#define EPB   16                   // elements per block
#define TROW  32                   // words per t-row (28 used + 4 pad)
#define IMG   904                  // 28*TROW + 8: 8-bank skew per element
#define XW    (EPB * IMG)          // 14464 words
#define VSTR  12                   // LUT stride per (p,v) entry (10 used + 2 pad)
#define NTABW (8 * 16 * VSTR)      // 1536 words
#define SMEMW (XW + NTABW)         // 16000 words = 62.5 KB

// ---- packed fp32x2 helpers (sm_103a dual-fp32: 2x FFMA throughput) ----
__device__ __forceinline__ u64 pk(float lo, float hi) {
    u64 r; asm("mov.b64 %0, {%1, %2};" : "=l"(r) : "f"(lo), "f"(hi)); return r;
}
__device__ __forceinline__ void upk(float& lo, float& hi, u64 v) {
    asm("mov.b64 {%0, %1}, %2;" : "=f"(lo), "=f"(hi) : "l"(v));
}
__device__ __forceinline__ u64 fma2(u64 a, u64 b, u64 c) {
    u64 d; asm("fma.rn.f32x2 %0, %1, %2, %3;" : "=l"(d) : "l"(a), "l"(b), "l"(c)); return d;
}
__device__ __forceinline__ u64 add2(u64 a, u64 b) {
    u64 d; asm("add.rn.f32x2 %0, %1, %2;" : "=l"(d) : "l"(a), "l"(b)); return d;
}

extern __shared__ __align__(16) float smem_f[];

__global__ void __launch_bounds__(TPB, 3) snn_kernel(
    const float* __restrict__ x,  const float* __restrict__ W1,
    const float* __restrict__ b1, const float* __restrict__ W2,
    const float* __restrict__ b2, float* __restrict__ out, int B)
{
    float* smx = smem_f;           // [EPB][IMG]: x rows, t-major, un-duplicated
    float* tab = smem_f + XW;      // nibble LUT: [(p*16+v)*VSTR + j]

    const int tid = threadIdx.x;
    const int lid = tid & 31;
    const int wid = tid >> 5;
    const int q   = lid >> 3;      // elem within warp (0..3)
    const int r   = lid & 7;       // unit-slice (0..7)
    const int eLocal = wid * EPW + q;
    const int gbase  = blockIdx.x * EPB;

    // ======== nibble LUT: tab[(p*16+v)*VSTR + j] = sum_{b in v} W2[j][4p+b] ========
    for (int idx = tid; idx < 8 * 16 * 10; idx += TPB) {
        int j = idx % 10;
        int v = (idx / 10) & 15;
        int p = idx / 160;
        float s = 0.0f;
#pragma unroll
        for (int b = 0; b < 4; ++b)
            if ((v >> b) & 1) s += W2[j * 32 + 4 * p + b];
        tab[(p * 16 + v) * VSTR + j] = s;
    }

    // ======== stage x: [e][t][i] rows (coalesced float4 global reads) ========
    for (int task = tid; task < EPB * 28; task += TPB) {
        int e = task / 28, i = task - e * 28;
        if (gbase + e < B) {
            const float4* src = reinterpret_cast<const float4*>(
                x + (size_t)(gbase + e) * 784 + i * 28);
            float* dst = smx + e * IMG + i;
#pragma unroll
            for (int c = 0; c < 7; ++c) {
                float4 v4 = __ldg(src + c);
                dst[(4 * c + 0) * TROW] = v4.x;
                dst[(4 * c + 1) * TROW] = v4.y;
                dst[(4 * c + 2) * TROW] = v4.z;
                dst[(4 * c + 3) * TROW] = v4.w;
            }
        }
    }

    // ======== per-lane register weights: unit-pairs (r, r+16) and (r+8, r+24) ======
    u64 wA[28], wB[28];
    {
        const float4* p0 = reinterpret_cast<const float4*>(W1 + r * 28);
        const float4* p1 = reinterpret_cast<const float4*>(W1 + (r + 16) * 28);
        const float4* p2 = reinterpret_cast<const float4*>(W1 + (r + 8) * 28);
        const float4* p3 = reinterpret_cast<const float4*>(W1 + (r + 24) * 28);
#pragma unroll
        for (int c = 0; c < 7; ++c) {
            float4 a = __ldg(p0 + c), b = __ldg(p1 + c);
            float4 e = __ldg(p2 + c), f = __ldg(p3 + c);
            wA[4 * c + 0] = pk(a.x, b.x); wA[4 * c + 1] = pk(a.y, b.y);
            wA[4 * c + 2] = pk(a.z, b.z); wA[4 * c + 3] = pk(a.w, b.w);
            wB[4 * c + 0] = pk(e.x, f.x); wB[4 * c + 1] = pk(e.y, f.y);
            wB[4 * c + 2] = pk(e.z, f.z); wB[4 * c + 3] = pk(e.w, f.w);
        }
    }
    const u64 hb0 = pk(__ldg(&b1[r]),     __ldg(&b1[r + 16]));
    const u64 hb1 = pk(__ldg(&b1[r + 8]), __ldg(&b1[r + 24]));

    // layer-2 lane roles: lanes 0..19 -> (elem me, output-pair jj)
    const int jj = lid % 5;
    const int me = (lid / 5) & 3;
    const u64 b2p = pk(__ldg(&b2[2 * jj]), __ldg(&b2[2 * jj + 1]));
    const float* tabjj = tab + 2 * jj;
    const u32 sel = (u32)me | (((u32)me + 4) << 4);   // byte_perm: pick byte 'me' of a,b

    __syncthreads();

    u64 v1a = 0ull, v1b = 0ull, v2p = 0ull, accp = 0ull;

#pragma unroll 2
    for (int t = 0; t < 28; ++t) {
        // ---- layer 1: two exact sequential fma chains (units packed (u,u+16)) ----
        const float4* xr = reinterpret_cast<const float4*>(smx + eLocal * IMG + t * TROW);
        u64 h0 = hb0, h1 = hb1;
#pragma unroll
        for (int k = 0; k < 7; ++k) {
            float4 xv = xr[k];
            u64 d0 = pk(xv.x, xv.x);
            h0 = fma2(d0, wA[4 * k + 0], h0); h1 = fma2(d0, wB[4 * k + 0], h1);
            u64 d1 = pk(xv.y, xv.y);
            h0 = fma2(d1, wA[4 * k + 1], h0); h1 = fma2(d1, wB[4 * k + 1], h1);
            u64 d2 = pk(xv.z, xv.z);
            h0 = fma2(d2, wA[4 * k + 2], h0); h1 = fma2(d2, wB[4 * k + 2], h1);
            u64 d3 = pk(xv.w, xv.w);
            h0 = fma2(d3, wA[4 * k + 3], h0); h1 = fma2(d3, wB[4 * k + 3], h1);
        }

        // ---- IF layer 1 + spike ballots ----
        v1a = add2(v1a, h0);
        v1b = add2(v1b, h1);
        float fa0, fa1, fb0, fb1;
        upk(fa0, fa1, v1a);
        upk(fb0, fb1, v1b);
        bool sr0  = (fa0 >= 1.0f);      // unit r
        bool sr16 = (fa1 >= 1.0f);      // unit r+16
        bool sr8  = (fb0 >= 1.0f);      // unit r+8
        bool sr24 = (fb1 >= 1.0f);      // unit r+24
        u32 B0 = __ballot_sync(0xffffffffu, sr0);
        u32 B1 = __ballot_sync(0xffffffffu, sr8);
        u32 B2 = __ballot_sync(0xffffffffu, sr16);
        u32 B3 = __ballot_sync(0xffffffffu, sr24);
        v1a = pk(sr0 ? 0.0f : fa0, sr16 ? 0.0f : fa1);
        v1b = pk(sr8 ? 0.0f : fb0, sr24 ? 0.0f : fb1);

        // ---- 32-bit spike mask of elem 'me' via 3 PRMTs (bit k = unit k) ----
        u32 lo16 = __byte_perm(B0, B1, sel);
        u32 hi16 = __byte_perm(B2, B3, sel);
        u32 M    = __byte_perm(lo16, hi16, 0x5410);

        // ---- layer 2: bias-first, ascending-p nibble LUT (packed j-pair) ----
        u64 h2 = b2p;
#pragma unroll
        for (int p = 0; p < 8; ++p) {
            u32 n = (M >> (4 * p)) & 15u;
            h2 = add2(h2, *reinterpret_cast<const u64*>(tabjj + (p * 16 + n) * VSTR));
        }

        // ---- IF layer 2 + rate accumulation ----
        v2p = add2(v2p, h2);
        float g0, g1;
        upk(g0, g1, v2p);
        bool t0 = (g0 >= 1.0f), t1 = (g1 >= 1.0f);
        accp = add2(accp, pk(t0 ? 1.0f : 0.0f, t1 ? 1.0f : 0.0f));
        v2p = pk(t0 ? 0.0f : g0, t1 ? 0.0f : g1);
    }

    // ---- output: lanes 0..19 write their (elem, j-pair) firing rates ----
    int ge = gbase + wid * EPW + me;
    if (lid < 20 && ge < B) {
        float a0, a1;
        upk(a0, a1, accp);
        *reinterpret_cast<float2*>(out + (size_t)ge * 10 + 2 * jj) =
            make_float2(a0 * (1.0f / 28.0f), a1 * (1.0f / 28.0f));
    }
}

extern "C" void kernel_launch(void* const* d_in, const int* in_sizes, int n_in,
                              void* d_out, int out_size) {
    const float* x  = (const float*)d_in[0];
    const float* W1 = (const float*)d_in[1];
    const float* b1 = (const float*)d_in[2];
    const float* W2 = (const float*)d_in[3];
    const float* b2 = (const float*)d_in[4];
    float* out = (float*)d_out;

    int B = in_sizes[0] / 784;
    int smem = SMEMW * (int)sizeof(float);   // 62.5 KB -> 3 blocks/SM (12 warps)

    cudaFuncSetAttribute(snn_kernel, cudaFuncAttributeMaxDynamicSharedMemorySize, smem);

    int grid = (B + EPB - 1) / EPB;
    snn_kernel<<<grid, TPB, smem>>>(x, W1, b1, W2, b2, out, B);
}